// round 8
// baseline (speedup 1.0000x reference)
#include <cuda_runtime.h>
#include <cuda_bf16.h>

// LIF neuron scan:
//   u[t] = tau * u[t-1] + x[t];  o[t] = (u[t] > 1);  u[t] *= (1 - o[t])
// x: [B, T, N] fp32, out: [B, T, N] fp32.  B=32, T=32, N=65536.
//
// R8 (= R7 resubmit after infra failure): CHUNK=32 — whole T dimension in
// one burst. Each thread issues 32 back-to-back LDG.128 (16KB/warp read
// run), scans all 32 steps in registers, then 32 back-to-back STG.128
// (16KB/warp write run). One read run + one write run per thread = coarsest
// possible R/W interleave for the DRAM scheduler. Burst-size axis confirmed
// monotone: CHUNK 4/8/16 -> 6037/6105/6242 GB/s. Occupancy irrelevant
// (22.5% at CHUNK=16 was the best run). Revert trigger: spills (L1% spike /
// HBM drop) -> lock in CHUNK=16.

#define T_STEPS 32
#define B_BATCH 32

__global__ __launch_bounds__(128, 1) void lif_scan_kernel(
    const float4* __restrict__ x,
    const float*  __restrict__ tau_p,
    float4*       __restrict__ out,
    int nv,          // N/4 (float4 lanes per (b,t) row)
    int total)       // B * nv
{
    int i = blockIdx.x * blockDim.x + threadIdx.x;
    if (i >= total) return;

    // clamp learned decay to [0,1]
    float tau = __ldg(tau_p);
    tau = fminf(fmaxf(tau, 0.0f), 1.0f);

    int b = i / nv;          // nv is a power of two; compiler -> shift
    int j = i - b * nv;

    size_t base = (size_t)b * T_STEPS * nv + j;
    const float4* xb = x   + base;
    float4*       ob = out + base;

    // ---- read run: 32 independent 16B loads, back-to-back ----
    float4 buf[T_STEPS];
#pragma unroll
    for (int t = 0; t < T_STEPS; t++)
        buf[t] = __ldcs(&xb[(size_t)t * nv]);

    // ---- compute: full 32-step scan, registers only ----
    float ux = 0.0f, uy = 0.0f, uz = 0.0f, uw = 0.0f;
#pragma unroll
    for (int t = 0; t < T_STEPS; t++) {
        float4 xi = buf[t];

        ux = fmaf(tau, ux, xi.x);
        uy = fmaf(tau, uy, xi.y);
        uz = fmaf(tau, uz, xi.z);
        uw = fmaf(tau, uw, xi.w);

        float4 o;
        o.x = (ux > 1.0f) ? 1.0f : 0.0f;
        o.y = (uy > 1.0f) ? 1.0f : 0.0f;
        o.z = (uz > 1.0f) ? 1.0f : 0.0f;
        o.w = (uw > 1.0f) ? 1.0f : 0.0f;

        // multiplicative soft reset: u = (u>1 ? 0 : u)
        ux = (ux > 1.0f) ? 0.0f : ux;
        uy = (uy > 1.0f) ? 0.0f : uy;
        uz = (uz > 1.0f) ? 0.0f : uz;
        uw = (uw > 1.0f) ? 0.0f : uw;

        buf[t] = o;   // reuse input buffer as output buffer
    }

    // ---- write run: 32 back-to-back 16B streaming stores ----
#pragma unroll
    for (int t = 0; t < T_STEPS; t++)
        __stcs(&ob[(size_t)t * nv], buf[t]);
}

extern "C" void kernel_launch(void* const* d_in, const int* in_sizes, int n_in,
                              void* d_out, int out_size)
{
    const float* x   = (const float*)d_in[0];   // [B, T, N] fp32
    const float* tau = (const float*)d_in[1];   // [1] fp32

    int total_elems = in_sizes[0];                       // B*T*N
    int N  = total_elems / (B_BATCH * T_STEPS);
    int nv = N / 4;                                      // float4 per (b,t) row
    int total_threads = B_BATCH * nv;                    // B * nv

    int block = 128;
    int grid  = (total_threads + block - 1) / block;

    lif_scan_kernel<<<grid, block>>>(
        (const float4*)x, tau, (float4*)d_out, nv, total_threads);
}

// round 9
// speedup vs baseline: 1.0108x; 1.0108x over previous
#include <cuda_runtime.h>
#include <cuda_bf16.h>

// LIF neuron scan:
//   u[t] = tau * u[t-1] + x[t];  o[t] = (u[t] > 1);  u[t] *= (1 - o[t])
// x: [B, T, N] fp32, out: [B, T, N] fp32.  B=32, T=32, N=65536.
//
// R9: CHUNK=16 bursts (best measured: 6242 GB/s) + spike-mask compression.
// Outputs are only 0.0/1.0, so instead of holding 16 float4 outputs in
// registers (64 regs), compress each chunk's spikes into 4 x 32-bit masks
// (bit t = lane spiked at step t) and expand mask->float inside the store
// run. Cuts regs ~122 -> ~90 => 5 blocks/SM = ~20 warps (was 14), at
// identical burst structure. Model: BW = min(f(burst), g(warps)); this
// raises g while holding f.

#define T_STEPS 32
#define B_BATCH 32
#define CHUNK   16

__global__ __launch_bounds__(128) void lif_scan_kernel(
    const float4* __restrict__ x,
    const float*  __restrict__ tau_p,
    float4*       __restrict__ out,
    int nv,          // N/4 (float4 lanes per (b,t) row)
    int total)       // B * nv
{
    int i = blockIdx.x * blockDim.x + threadIdx.x;
    if (i >= total) return;

    // clamp learned decay to [0,1]
    float tau = __ldg(tau_p);
    tau = fminf(fmaxf(tau, 0.0f), 1.0f);

    int b = i / nv;          // nv is a power of two; compiler -> shift
    int j = i - b * nv;

    size_t base = (size_t)b * T_STEPS * nv + j;
    const float4* xb = x   + base;
    float4*       ob = out + base;

    float ux = 0.0f, uy = 0.0f, uz = 0.0f, uw = 0.0f;

#pragma unroll
    for (int c = 0; c < T_STEPS / CHUNK; c++) {
        const size_t coff = (size_t)c * CHUNK * nv;

        // ---- read run: 16 independent 16B loads, back-to-back ----
        float4 buf[CHUNK];
#pragma unroll
        for (int t = 0; t < CHUNK; t++)
            buf[t] = __ldcs(&xb[coff + (size_t)t * nv]);

        // ---- compute: scan the chunk, compress spikes into bit masks ----
        unsigned mx = 0, my = 0, mz = 0, mw = 0;
#pragma unroll
        for (int t = 0; t < CHUNK; t++) {
            float4 xi = buf[t];

            ux = fmaf(tau, ux, xi.x);
            uy = fmaf(tau, uy, xi.y);
            uz = fmaf(tau, uz, xi.z);
            uw = fmaf(tau, uw, xi.w);

            bool sx = (ux > 1.0f), sy = (uy > 1.0f),
                 sz = (uz > 1.0f), sw = (uw > 1.0f);

            mx |= (unsigned)sx << t;
            my |= (unsigned)sy << t;
            mz |= (unsigned)sz << t;
            mw |= (unsigned)sw << t;

            // multiplicative soft reset: u = (spiked ? 0 : u)
            ux = sx ? 0.0f : ux;
            uy = sy ? 0.0f : uy;
            uz = sz ? 0.0f : uz;
            uw = sw ? 0.0f : uw;
        }

        // ---- write run: 16 back-to-back streaming stores, expand masks ----
#pragma unroll
        for (int t = 0; t < CHUNK; t++) {
            float4 o;
            o.x = (mx >> t) & 1u ? 1.0f : 0.0f;
            o.y = (my >> t) & 1u ? 1.0f : 0.0f;
            o.z = (mz >> t) & 1u ? 1.0f : 0.0f;
            o.w = (mw >> t) & 1u ? 1.0f : 0.0f;
            __stcs(&ob[coff + (size_t)t * nv], o);
        }
    }
}

extern "C" void kernel_launch(void* const* d_in, const int* in_sizes, int n_in,
                              void* d_out, int out_size)
{
    const float* x   = (const float*)d_in[0];   // [B, T, N] fp32
    const float* tau = (const float*)d_in[1];   // [1] fp32

    int total_elems = in_sizes[0];                       // B*T*N
    int N  = total_elems / (B_BATCH * T_STEPS);
    int nv = N / 4;                                      // float4 per (b,t) row
    int total_threads = B_BATCH * nv;                    // B * nv

    int block = 128;
    int grid  = (total_threads + block - 1) / block;

    lif_scan_kernel<<<grid, block>>>(
        (const float4*)x, tau, (float4*)d_out, nv, total_threads);
}